// round 12
// baseline (speedup 1.0000x reference)
#include <cuda_runtime.h>

#define BB 4096
#define SS 32
#define TT 32
#define VOC 256
#define EE 128
#define HH 64
#define AA 64
#define GH3 192   /* 3*H */

// ---------------- scratch (device globals; no allocation allowed) ----------------
__device__ float g_fwd[BB * SS * HH];      // forward encoder states
__device__ float g_bwd[BB * SS * HH];      // backward encoder states
__device__ float g_enc[BB * SS * HH];      // encoded = fwd + bwd
__device__ float g_encproj[BB * SS * AA];  // encoded @ attn_We + be
__device__ float g_hid[BB * TT * HH];      // decoder hidden states
__device__ float g_TWf[VOC * GH3];         // table: emb[id] @ enc_Wf + bf[0]
__device__ float g_TWb[VOC * GH3];         // table: emb[id] @ enc_Wb + bb[0]
__device__ float g_TD[VOC * GH3];          // table: tied_emb[id] @ dec_W[0:64] + db[0]

// ---------------- packed f32x2 helpers (sm_100+) ----------------
__device__ __forceinline__ unsigned long long pack2(float x) {
    unsigned long long r;
    asm("mov.b64 %0, {%1, %1};" : "=l"(r) : "f"(x));
    return r;
}
__device__ __forceinline__ void fma2(unsigned long long& acc,
                                     unsigned long long a, unsigned long long b) {
    asm("fma.rn.f32x2 %0, %1, %2, %0;" : "+l"(acc) : "l"(a), "l"(b));
}
__device__ __forceinline__ void unpack2(unsigned long long v, float& lo, float& hi) {
    asm("mov.b64 {%0, %1}, %2;" : "=f"(lo), "=f"(hi) : "l"(v));
}

// ---------------- activations ----------------
__device__ __forceinline__ float fsigmoid(float x) {
    return __fdividef(1.0f, 1.0f + __expf(-x));
}
__device__ __forceinline__ float ftanh(float x) {
    float e = __expf(2.0f * x);
    return 1.0f - __fdividef(2.0f, e + 1.0f);
}
__device__ __forceinline__ float tanha(float x) {
    float r; asm("tanh.approx.f32 %0, %1;" : "=f"(r) : "f"(x)); return r;
}

// =================================================================
// Precompute per-vocab-id input-projection tables (V=256 rows).
// =================================================================
__global__ __launch_bounds__(192)
void table_kernel(const float* __restrict__ src_emb,
                  const float* __restrict__ Wf, const float* __restrict__ bf,
                  const float* __restrict__ Wb, const float* __restrict__ bb,
                  const float* __restrict__ dW, const float* __restrict__ db,
                  const float* __restrict__ outW)
{
    __shared__ float se[EE];
    __shared__ float sx[HH];
    const int id = blockIdx.x;
    const int j = threadIdx.x;
    for (int i = j; i < EE; i += 192) se[i] = src_emb[id * EE + i];
    for (int i = j; i < HH; i += 192) sx[i] = outW[i * VOC + id] * 8.0f;
    __syncthreads();

    float af = bf[j], ab = bb[j];
    #pragma unroll 4
    for (int k = 0; k < EE; ++k) {
        af += se[k] * Wf[k * GH3 + j];
        ab += se[k] * Wb[k * GH3 + j];
    }
    float ad = db[j];
    #pragma unroll 4
    for (int h = 0; h < HH; ++h) ad += sx[h] * dW[h * GH3 + j];
    g_TWf[id * GH3 + j] = af;
    g_TWb[id * GH3 + j] = ab;
    g_TD[id * GH3 + j]  = ad;
}

// =================================================================
// Encoder (unchanged from R11): table-driven x-projection, loop does
// only h @ U. G=16, 384 threads, 104 KB smem -> 2 CTAs/SM.
// =================================================================
__global__ __launch_bounds__(384)
void enc_kernel(const int* __restrict__ src_ids,
                const float* __restrict__ Uf, const float* __restrict__ bf,
                const float* __restrict__ Ub, const float* __restrict__ bb)
{
    constexpr int G = 16;
    constexpr int NT = 384;
    const bool BWD = (blockIdx.y != 0);
    const float* U    = BWD ? Ub : Uf;
    const float* bias = BWD ? bb : bf;
    const float* TW   = BWD ? g_TWb : g_TWf;
    float* dst        = BWD ? g_bwd : g_fwd;

    extern __shared__ float sm[];
    float* sU  = sm;                 // 64*192
    float* sB  = sU + HH * GH3;      // 384
    float* sXT = sB + 2 * GH3;       // 2 * 16*192 (double buffer, [g][192])
    float* sHT = sXT + 2 * G * GH3;  // 64*16 ([k][g])
    float* sHP = sHT + HH * G;       // 2 halves * 16*192

    const int tid = threadIdx.x;
    for (int i = tid; i < HH * GH3; i += NT) sU[i] = U[i];
    for (int i = tid; i < 2 * GH3; i += NT) sB[i] = bias[i];
    for (int i = tid; i < G * HH; i += NT) sHT[i] = 0.0f;

    const int b0 = blockIdx.x * G;
    const int half = tid / 192;
    const int j    = tid - half * 192;

    {
        const int s0 = BWD ? SS - 1 : 0;
        for (int i = tid; i < G * 48; i += NT) {
            int g = i / 48, q = i - g * 48;
            int id = src_ids[(b0 + g) * SS + s0];
            ((float4*)sXT)[g * 48 + q] = ((const float4*)(TW + id * GH3))[q];
        }
    }
    __syncthreads();

    int cur = 0;
    for (int step = 0; step < SS; ++step) {
        const int s  = BWD ? (SS - 1 - step) : step;
        const int sn = BWD ? (s - 1) : (s + 1);
        float* Xc = &sXT[cur * (G * GH3)];
        float* Xn = &sXT[(cur ^ 1) * (G * GH3)];

        float4 pf[2];
        if (step + 1 < SS) {
            int n = 0;
            for (int i = tid; i < G * 48; i += NT) {
                int g = i / 48, q = i - g * 48;
                int id = __ldg(&src_ids[(b0 + g) * SS + sn]);
                pf[n++] = __ldg((const float4*)(TW + id * GH3) + q);
            }
        }

        unsigned long long hp2[8];
        {
            unsigned long long bh = (half == 0) ? pack2(sB[GH3 + j]) : 0ULL;
            #pragma unroll
            for (int p = 0; p < 8; ++p) hp2[p] = bh;
        }
        const int ku0 = half * 32;
        #pragma unroll 4
        for (int kk = 0; kk < 32; ++kk) {
            int k = ku0 + kk;
            unsigned long long u2 = pack2(sU[k * GH3 + j]);
            const ulonglong2* hr = (const ulonglong2*)&sHT[k * G];
            ulonglong2 h0 = hr[0], h1 = hr[1], h2 = hr[2], h3 = hr[3];
            fma2(hp2[0], u2, h0.x); fma2(hp2[1], u2, h0.y);
            fma2(hp2[2], u2, h1.x); fma2(hp2[3], u2, h1.y);
            fma2(hp2[4], u2, h2.x); fma2(hp2[5], u2, h2.y);
            fma2(hp2[6], u2, h3.x); fma2(hp2[7], u2, h3.y);
        }
        #pragma unroll
        for (int p = 0; p < 8; ++p) {
            float lo, hi;
            unpack2(hp2[p], lo, hi);
            sHP[(half * G + 2 * p) * GH3 + j] = lo;
            sHP[(half * G + 2 * p + 1) * GH3 + j] = hi;
        }
        if (step + 1 < SS) {
            int n = 0;
            for (int i = tid; i < G * 48; i += NT) {
                int g = i / 48, q = i - g * 48;
                ((float4*)Xn)[g * 48 + q] = pf[n++];
            }
        }
        __syncthreads();

        for (int idx = tid; idx < G * HH; idx += NT) {
            int g  = idx >> 6;
            int jj = idx & 63;
            const float* XP  = &Xc[g * GH3];
            const float* HP0 = &sHP[g * GH3];
            const float* HP1 = &sHP[(G + g) * GH3];
            float hz = HP0[jj] + HP1[jj];
            float hr_ = HP0[HH + jj] + HP1[HH + jj];
            float hh = HP0[2 * HH + jj] + HP1[2 * HH + jj];
            float z = fsigmoid(XP[jj] + hz);
            float r = fsigmoid(XP[HH + jj] + hr_);
            float n = ftanh(XP[2 * HH + jj] + r * hh);
            float hold = sHT[jj * G + g];
            float hn = z * hold + (1.0f - z) * n;
            sHT[jj * G + g] = hn;
            dst[(b0 + g) * SS * HH + s * HH + jj] = hn;
        }
        __syncthreads();
        cur ^= 1;
    }
}

// =================================================================
// encoded = fwd + bwd (fused); enc_proj = encoded @ attn_We + be
// =================================================================
__global__ __launch_bounds__(256)
void proj_kernel(const float* __restrict__ We, const float* __restrict__ be)
{
    extern __shared__ float sm[];
    float* sWe = sm;              // 64*64
    float* sbe = sWe + HH * AA;   // 64
    float* sR  = sbe + 64;        // 64 rows * 64

    const int tid = threadIdx.x;
    for (int i = tid; i < HH * AA; i += 256) sWe[i] = We[i];
    if (tid < 64) sbe[tid] = be[tid];
    const int rbase = blockIdx.x * 64;
    for (int i = tid; i < 64 * HH; i += 256) {
        float e = g_fwd[rbase * HH + i] + g_bwd[rbase * HH + i];
        sR[i] = e;
        g_enc[rbase * HH + i] = e;
    }
    __syncthreads();

    const int a  = tid & 63;
    const int rq = tid >> 6;
    float acc[16];
    #pragma unroll
    for (int r = 0; r < 16; ++r) acc[r] = sbe[a];
    for (int k = 0; k < HH; ++k) {
        float w = sWe[k * AA + a];
        #pragma unroll
        for (int r = 0; r < 16; ++r) acc[r] += w * sR[(rq * 16 + r) * HH + k];
    }
    #pragma unroll
    for (int r = 0; r < 16; ++r)
        g_encproj[(rbase + rq * 16 + r) * AA + a] = acc[r];
}

// =================================================================
// Decoder v3: G=8, 384 threads, 1 CTA/SM @ 184 KB smem.
//  - encoded cached in smem (kills per-step L2 reads)
//  - GEMV weights (dec_W ctx-half + dec_U columns) in registers
//  - warp-specialized phase A: warps 0-7 = per-g dproj->scores->
//    softmax->ctx (warp-local, __syncwarp only); warps 8-11 = TD gather
//  - 3 block barriers per step (was 6)
// =================================================================
__global__ __launch_bounds__(384)
void dec_kernel(const int* __restrict__ tgt_ids,
                const float* __restrict__ dW, const float* __restrict__ dU,
                const float* __restrict__ db,
                const float* __restrict__ Wd, const float* __restrict__ bd,
                const float* __restrict__ av, const float* __restrict__ bv)
{
    constexpr int G = 8;
    constexpr int NT = 384;
    constexpr int EPL = AA + 1;  // 65
    extern __shared__ float sm[];
    float* sB   = sm;                  // 384
    float* sWd  = sB + 2 * GH3;        // 4096
    float* sbd  = sWd + HH * AA;       // 64
    float* sv   = sbd + AA;            // 64
    float* sEP  = sv + AA;             // 8*32*65 = 16640
    float* sEnc = sEP + G * SS * EPL;  // 8*32*64 = 16384 (same layout as g_enc)
    float* sXPx = sEnc + G * SS * HH;  // 8*192 = 1536 (gathered TD rows)
    float* sCtxT= sXPx + G * GH3;      // 64*8 = 512  ([h][g])
    float* sXPc = sCtxT + HH * G;      // 2*8*192 = 3072
    float* sHP  = sXPc + 2 * G * GH3;  // 3072
    float* sHT  = sHP + 2 * G * GH3;   // 512 ([h][g])
    float* sDP  = sHT + HH * G;        // 512
    float* sLg  = sDP + G * AA;        // 256 (normalized weights)

    const int tid = threadIdx.x;
    const int b0 = blockIdx.x * G;
    const int half = tid / 192;        // warp-uniform
    const int j    = tid - half * 192; // gate column 0..191
    const int wid  = tid >> 5;
    const int lane = tid & 31;

    // GEMV weight columns -> registers (k-split: 32 each)
    float wc[32], uu[32];
    const int k0 = half * 32;
    #pragma unroll
    for (int kk = 0; kk < 32; ++kk) {
        wc[kk] = __ldg(&dW[(HH + k0 + kk) * GH3 + j]);  // ctx half rows 64..127
        uu[kk] = __ldg(&dU[(k0 + kk) * GH3 + j]);
    }

    for (int i = tid; i < 2 * GH3; i += NT) sB[i] = db[i];
    for (int i = tid; i < HH * AA; i += NT) sWd[i] = Wd[i];
    if (tid < AA) { sbd[tid] = bd[tid]; sv[tid] = av[tid]; }
    const float bvv = bv[0];

    for (int i = tid; i < G * SS * AA; i += NT) {
        int g = i / (SS * AA);
        int rem = i - g * SS * AA;
        int s = rem >> 6;
        int a = rem & 63;
        sEP[g * SS * EPL + s * EPL + a] = g_encproj[(b0 + g) * SS * AA + rem];
    }
    // cache encoded (layout identical to global)
    for (int i = tid; i < G * SS * HH; i += NT)
        sEnc[i] = g_enc[b0 * SS * HH + i];
    // h0 = encoded[:, 0] (transposed)
    for (int i = tid; i < G * HH; i += NT) {
        int g = i >> 6; int jj = i & 63;
        sHT[jj * G + g] = g_enc[(b0 + g) * SS * HH + jj];
    }
    __syncthreads();

    for (int t = 0; t < TT; ++t) {
        // ---------- phase A: warp-specialized ----------
        if (wid < G) {
            const int g = wid;
            // dproj: lane covers a = lane, lane+32
            float a0 = sbd[lane], a1 = sbd[lane + 32];
            #pragma unroll 8
            for (int h = 0; h < HH; ++h) {
                float hv = sHT[h * G + g];            // broadcast
                a0 += hv * sWd[h * AA + lane];
                a1 += hv * sWd[h * AA + lane + 32];
            }
            sDP[g * AA + lane] = a0;
            sDP[g * AA + lane + 32] = a1;
            __syncwarp();

            // scores: lane = source position s
            const float* ep = &sEP[g * SS * EPL + lane * EPL];
            const float* dp = &sDP[g * AA];
            float acc = bvv;
            #pragma unroll 8
            for (int a = 0; a < AA; ++a) acc += sv[a] * tanha(dp[a] + ep[a]);

            // softmax (warp-wide)
            float m = acc;
            #pragma unroll
            for (int off = 16; off > 0; off >>= 1)
                m = fmaxf(m, __shfl_xor_sync(0xffffffffu, m, off));
            float e = __expf(acc - m);
            float sum = e;
            #pragma unroll
            for (int off = 16; off > 0; off >>= 1)
                sum += __shfl_xor_sync(0xffffffffu, sum, off);
            sLg[g * SS + lane] = e * __fdividef(1.0f, sum);
            __syncwarp();

            // context: lane covers h = lane, lane+32
            const float* encb = &sEnc[g * SS * HH];
            float c0 = 0.0f, c1 = 0.0f;
            #pragma unroll
            for (int s = 0; s < SS; ++s) {
                float ww = sLg[g * SS + s];            // broadcast
                c0 += ww * encb[s * HH + lane];
                c1 += ww * encb[s * HH + lane + 32];
            }
            sCtxT[lane * G + g] = c0;
            sCtxT[(lane + 32) * G + g] = c1;
        } else {
            // warps 8-11: TD-table gather (8*48 float4 over 128 threads)
            int tt = tid - 256;
            for (int i = tt; i < G * 48; i += 128) {
                int g = i / 48, q = i - g * 48;
                int id = (t == 0) ? 1 : __ldg(&tgt_ids[(b0 + g) * TT + (t - 1)]);
                ((float4*)sXPx)[i] = __ldg((const float4*)(g_TD + id * GH3) + q);
            }
        }
        __syncthreads();  // B1

        // ---------- GEMV (register weights, f32x2, k-split) ----------
        unsigned long long xc2[4], hp2[4];
        {
            unsigned long long bh = (half == 0) ? pack2(sB[GH3 + j]) : 0ULL;
            #pragma unroll
            for (int p = 0; p < 4; ++p) { xc2[p] = 0ULL; hp2[p] = bh; }
        }
        #pragma unroll
        for (int kk = 0; kk < 32; ++kk) {
            const int k = k0 + kk;
            unsigned long long w2 = pack2(wc[kk]);
            const ulonglong2* cr = (const ulonglong2*)&sCtxT[k * G];
            ulonglong2 c0 = cr[0], c1 = cr[1];
            fma2(xc2[0], w2, c0.x); fma2(xc2[1], w2, c0.y);
            fma2(xc2[2], w2, c1.x); fma2(xc2[3], w2, c1.y);
            unsigned long long u2 = pack2(uu[kk]);
            const ulonglong2* hr = (const ulonglong2*)&sHT[k * G];
            ulonglong2 h0 = hr[0], h1 = hr[1];
            fma2(hp2[0], u2, h0.x); fma2(hp2[1], u2, h0.y);
            fma2(hp2[2], u2, h1.x); fma2(hp2[3], u2, h1.y);
        }
        #pragma unroll
        for (int p = 0; p < 4; ++p) {
            float lo, hi;
            unpack2(xc2[p], lo, hi);
            sXPc[(half * G + 2 * p) * GH3 + j] = lo;
            sXPc[(half * G + 2 * p + 1) * GH3 + j] = hi;
            unpack2(hp2[p], lo, hi);
            sHP[(half * G + 2 * p) * GH3 + j] = lo;
            sHP[(half * G + 2 * p + 1) * GH3 + j] = hi;
        }
        __syncthreads();  // B2

        // ---------- gates (512 tasks) ----------
        for (int idx = tid; idx < G * HH; idx += NT) {
            int g  = idx >> 6;
            int jj = idx & 63;
            const float* XPx = &sXPx[g * GH3];
            const float* XC0 = &sXPc[g * GH3];
            const float* XC1 = &sXPc[(G + g) * GH3];
            const float* HP0 = &sHP[g * GH3];
            const float* HP1 = &sHP[(G + g) * GH3];
            float xz = XPx[jj] + XC0[jj] + XC1[jj];
            float xr = XPx[HH + jj] + XC0[HH + jj] + XC1[HH + jj];
            float xh = XPx[2*HH + jj] + XC0[2*HH + jj] + XC1[2*HH + jj];
            float hz = HP0[jj] + HP1[jj];
            float hr_ = HP0[HH + jj] + HP1[HH + jj];
            float hh = HP0[2*HH + jj] + HP1[2*HH + jj];
            float z = fsigmoid(xz + hz);
            float r = fsigmoid(xr + hr_);
            float n = ftanh(xh + r * hh);
            float hold = sHT[jj * G + g];
            float hn = z * hold + (1.0f - z) * n;
            sHT[jj * G + g] = hn;
            g_hid[(b0 + g) * TT * HH + t * HH + jj] = hn;
        }
        __syncthreads();  // B3
    }
}

// =================================================================
// logits = hidden @ out_W + out_b (transposed tile + f32x2)
// =================================================================
__global__ __launch_bounds__(256)
void out_kernel(const float* __restrict__ outW, const float* __restrict__ outb,
                float* __restrict__ out)
{
    constexpr int R = 32;
    constexpr int TIL = 4;
    constexpr int PIT = 36;
    extern __shared__ float sm[];
    float* sOW = sm;              // 64*256
    float* sOB = sOW + HH * VOC;  // 256
    float* sRT = sOB + VOC;       // 64 * 36

    const int tid = threadIdx.x;
    for (int i = tid; i < HH * VOC; i += 256) sOW[i] = outW[i];
    sOB[tid] = outb[tid];

    for (int tile = 0; tile < TIL; ++tile) {
        const int rbase = (blockIdx.x * TIL + tile) * R;
        __syncthreads();
        for (int i = tid; i < R * HH; i += 256) {
            int r = i >> 6, k = i & 63;
            sRT[k * PIT + r] = g_hid[(rbase + r) * HH + k];
        }
        __syncthreads();

        const int v = tid;
        const unsigned long long b2 = pack2(sOB[v]);
        unsigned long long acc2[16];
        #pragma unroll
        for (int p = 0; p < 16; ++p) acc2[p] = b2;

        #pragma unroll 4
        for (int k = 0; k < HH; ++k) {
            unsigned long long w2 = pack2(sOW[k * VOC + v]);
            const ulonglong2* row = (const ulonglong2*)&sRT[k * PIT];
            #pragma unroll
            for (int q = 0; q < 8; ++q) {
                ulonglong2 rp = row[q];
                fma2(acc2[2 * q], w2, rp.x);
                fma2(acc2[2 * q + 1], w2, rp.y);
            }
        }
        #pragma unroll
        for (int p = 0; p < 16; ++p) {
            float lo, hi;
            unpack2(acc2[p], lo, hi);
            out[(rbase + 2 * p) * VOC + v] = lo;
            out[(rbase + 2 * p + 1) * VOC + v] = hi;
        }
    }
}

// =================================================================
// launch
// =================================================================
extern "C" void kernel_launch(void* const* d_in, const int* in_sizes, int n_in,
                              void* d_out, int out_size)
{
    const int* src_ids = (const int*)d_in[0];   // int32 (JAX x64 disabled)
    const int* tgt_ids = (const int*)d_in[1];   // int32
    const float* src_emb = (const float*)d_in[2];
    const float* enc_Wf  = (const float*)d_in[3];
    const float* enc_Uf  = (const float*)d_in[4];
    const float* enc_bf  = (const float*)d_in[5];
    const float* enc_Wb  = (const float*)d_in[6];
    const float* enc_Ub  = (const float*)d_in[7];
    const float* enc_bb  = (const float*)d_in[8];
    const float* attn_We = (const float*)d_in[9];
    const float* attn_be = (const float*)d_in[10];
    const float* attn_Wd = (const float*)d_in[11];
    const float* attn_bd = (const float*)d_in[12];
    const float* attn_v  = (const float*)d_in[13];
    const float* attn_bv = (const float*)d_in[14];
    const float* dec_W   = (const float*)d_in[15];
    const float* dec_U   = (const float*)d_in[16];
    const float* dec_b   = (const float*)d_in[17];
    const float* out_W   = (const float*)d_in[18];
    const float* out_b   = (const float*)d_in[19];
    float* out = (float*)d_out;

    const int ENC_SMEM  = (12288 + 384 + 6144 + 1024 + 6144) * 4;                // 103936
    const int PROJ_SMEM = (4096 + 64 + 4096) * 4;                                 // 33024
    const int DEC_SMEM  = (384 + 4096 + 64 + 64 + 16640 + 16384 + 1536 + 512
                           + 3072 + 3072 + 512 + 512 + 256) * 4;                  // 188416
    const int OUT_SMEM  = (16384 + 256 + 64 * 36) * 4;                            // 75776

    cudaFuncSetAttribute(enc_kernel, cudaFuncAttributeMaxDynamicSharedMemorySize, ENC_SMEM);
    cudaFuncSetAttribute(dec_kernel, cudaFuncAttributeMaxDynamicSharedMemorySize, DEC_SMEM);
    cudaFuncSetAttribute(out_kernel, cudaFuncAttributeMaxDynamicSharedMemorySize, OUT_SMEM);

    table_kernel<<<VOC, 192>>>(src_emb, enc_Wf, enc_bf, enc_Wb, enc_bb,
                               dec_W, dec_b, out_W);
    dim3 enc_grid(BB / 16, 2);
    enc_kernel<<<enc_grid, 384, ENC_SMEM>>>(src_ids, enc_Uf, enc_bf, enc_Ub, enc_bb);
    proj_kernel<<<(BB * SS) / 64, 256, PROJ_SMEM>>>(attn_We, attn_be);
    dec_kernel<<<BB / 8, 384, DEC_SMEM>>>(tgt_ids, dec_W, dec_U, dec_b,
                                          attn_Wd, attn_bd, attn_v, attn_bv);
    out_kernel<<<(BB * TT) / (32 * 4), 256, OUT_SMEM>>>(out_W, out_b, out);
}

// round 15
// speedup vs baseline: 1.5662x; 1.5662x over previous
#include <cuda_runtime.h>

#define BB 4096
#define SS 32
#define TT 32
#define VOC 256
#define EE 128
#define HH 64
#define AA 64
#define GH3 192   /* 3*H */

// ---------------- scratch (device globals; no allocation allowed) ----------------
__device__ float g_fwd[BB * SS * HH];      // forward encoder states
__device__ float g_bwd[BB * SS * HH];      // backward encoder states
__device__ float g_enc[BB * SS * HH];      // encoded = fwd + bwd
__device__ float g_encproj[BB * SS * AA];  // encoded @ attn_We + be
__device__ float g_hid[BB * TT * HH];      // decoder hidden states
__device__ float g_TWf[VOC * GH3];         // table: emb[id] @ enc_Wf + bf[0]
__device__ float g_TWb[VOC * GH3];         // table: emb[id] @ enc_Wb + bb[0]
__device__ float g_TD[VOC * GH3];          // table: tied_emb[id] @ dec_W[0:64] + db[0]

// ---------------- packed f32x2 helpers (sm_100+) ----------------
__device__ __forceinline__ unsigned long long pack2(float x) {
    unsigned long long r;
    asm("mov.b64 %0, {%1, %1};" : "=l"(r) : "f"(x));
    return r;
}
__device__ __forceinline__ void fma2(unsigned long long& acc,
                                     unsigned long long a, unsigned long long b) {
    asm("fma.rn.f32x2 %0, %1, %2, %0;" : "+l"(acc) : "l"(a), "l"(b));
}
__device__ __forceinline__ void unpack2(unsigned long long v, float& lo, float& hi) {
    asm("mov.b64 {%0, %1}, %2;" : "=f"(lo), "=f"(hi) : "l"(v));
}

// ---------------- activations ----------------
__device__ __forceinline__ float fsigmoid(float x) {
    return __fdividef(1.0f, 1.0f + __expf(-x));
}
__device__ __forceinline__ float ftanh(float x) {
    float e = __expf(2.0f * x);
    return 1.0f - __fdividef(2.0f, e + 1.0f);
}
__device__ __forceinline__ float tanha(float x) {
    float r; asm("tanh.approx.f32 %0, %1;" : "=f"(r) : "f"(x)); return r;
}

// =================================================================
// Precompute per-vocab-id input-projection tables (V=256 rows).
// =================================================================
__global__ __launch_bounds__(192)
void table_kernel(const float* __restrict__ src_emb,
                  const float* __restrict__ Wf, const float* __restrict__ bf,
                  const float* __restrict__ Wb, const float* __restrict__ bb,
                  const float* __restrict__ dW, const float* __restrict__ db,
                  const float* __restrict__ outW)
{
    __shared__ float se[EE];
    __shared__ float sx[HH];
    const int id = blockIdx.x;
    const int j = threadIdx.x;
    for (int i = j; i < EE; i += 192) se[i] = src_emb[id * EE + i];
    for (int i = j; i < HH; i += 192) sx[i] = outW[i * VOC + id] * 8.0f;
    __syncthreads();

    float af = bf[j], ab = bb[j];
    #pragma unroll 4
    for (int k = 0; k < EE; ++k) {
        af += se[k] * Wf[k * GH3 + j];
        ab += se[k] * Wb[k * GH3 + j];
    }
    float ad = db[j];
    #pragma unroll 4
    for (int h = 0; h < HH; ++h) ad += sx[h] * dW[h * GH3 + j];
    g_TWf[id * GH3 + j] = af;
    g_TWb[id * GH3 + j] = ab;
    g_TD[id * GH3 + j]  = ad;
}

// =================================================================
// Encoder (unchanged from R11): table-driven x-projection, loop does
// only h @ U. G=16, 384 threads, 104 KB smem -> 2 CTAs/SM.
// =================================================================
__global__ __launch_bounds__(384)
void enc_kernel(const int* __restrict__ src_ids,
                const float* __restrict__ Uf, const float* __restrict__ bf,
                const float* __restrict__ Ub, const float* __restrict__ bb)
{
    constexpr int G = 16;
    constexpr int NT = 384;
    const bool BWD = (blockIdx.y != 0);
    const float* U    = BWD ? Ub : Uf;
    const float* bias = BWD ? bb : bf;
    const float* TW   = BWD ? g_TWb : g_TWf;
    float* dst        = BWD ? g_bwd : g_fwd;

    extern __shared__ float sm[];
    float* sU  = sm;                 // 64*192
    float* sB  = sU + HH * GH3;      // 384
    float* sXT = sB + 2 * GH3;       // 2 * 16*192 (double buffer, [g][192])
    float* sHT = sXT + 2 * G * GH3;  // 64*16 ([k][g])
    float* sHP = sHT + HH * G;       // 2 halves * 16*192

    const int tid = threadIdx.x;
    for (int i = tid; i < HH * GH3; i += NT) sU[i] = U[i];
    for (int i = tid; i < 2 * GH3; i += NT) sB[i] = bias[i];
    for (int i = tid; i < G * HH; i += NT) sHT[i] = 0.0f;

    const int b0 = blockIdx.x * G;
    const int half = tid / 192;
    const int j    = tid - half * 192;

    {
        const int s0 = BWD ? SS - 1 : 0;
        for (int i = tid; i < G * 48; i += NT) {
            int g = i / 48, q = i - g * 48;
            int id = src_ids[(b0 + g) * SS + s0];
            ((float4*)sXT)[g * 48 + q] = ((const float4*)(TW + id * GH3))[q];
        }
    }
    __syncthreads();

    int cur = 0;
    for (int step = 0; step < SS; ++step) {
        const int s  = BWD ? (SS - 1 - step) : step;
        const int sn = BWD ? (s - 1) : (s + 1);
        float* Xc = &sXT[cur * (G * GH3)];
        float* Xn = &sXT[(cur ^ 1) * (G * GH3)];

        float4 pf[2];
        if (step + 1 < SS) {
            int n = 0;
            for (int i = tid; i < G * 48; i += NT) {
                int g = i / 48, q = i - g * 48;
                int id = __ldg(&src_ids[(b0 + g) * SS + sn]);
                pf[n++] = __ldg((const float4*)(TW + id * GH3) + q);
            }
        }

        unsigned long long hp2[8];
        {
            unsigned long long bh = (half == 0) ? pack2(sB[GH3 + j]) : 0ULL;
            #pragma unroll
            for (int p = 0; p < 8; ++p) hp2[p] = bh;
        }
        const int ku0 = half * 32;
        #pragma unroll 4
        for (int kk = 0; kk < 32; ++kk) {
            int k = ku0 + kk;
            unsigned long long u2 = pack2(sU[k * GH3 + j]);
            const ulonglong2* hr = (const ulonglong2*)&sHT[k * G];
            ulonglong2 h0 = hr[0], h1 = hr[1], h2 = hr[2], h3 = hr[3];
            fma2(hp2[0], u2, h0.x); fma2(hp2[1], u2, h0.y);
            fma2(hp2[2], u2, h1.x); fma2(hp2[3], u2, h1.y);
            fma2(hp2[4], u2, h2.x); fma2(hp2[5], u2, h2.y);
            fma2(hp2[6], u2, h3.x); fma2(hp2[7], u2, h3.y);
        }
        #pragma unroll
        for (int p = 0; p < 8; ++p) {
            float lo, hi;
            unpack2(hp2[p], lo, hi);
            sHP[(half * G + 2 * p) * GH3 + j] = lo;
            sHP[(half * G + 2 * p + 1) * GH3 + j] = hi;
        }
        if (step + 1 < SS) {
            int n = 0;
            for (int i = tid; i < G * 48; i += NT) {
                int g = i / 48, q = i - g * 48;
                ((float4*)Xn)[g * 48 + q] = pf[n++];
            }
        }
        __syncthreads();

        for (int idx = tid; idx < G * HH; idx += NT) {
            int g  = idx >> 6;
            int jj = idx & 63;
            const float* XP  = &Xc[g * GH3];
            const float* HP0 = &sHP[g * GH3];
            const float* HP1 = &sHP[(G + g) * GH3];
            float hz = HP0[jj] + HP1[jj];
            float hr_ = HP0[HH + jj] + HP1[HH + jj];
            float hh = HP0[2 * HH + jj] + HP1[2 * HH + jj];
            float z = fsigmoid(XP[jj] + hz);
            float r = fsigmoid(XP[HH + jj] + hr_);
            float n = ftanh(XP[2 * HH + jj] + r * hh);
            float hold = sHT[jj * G + g];
            float hn = z * hold + (1.0f - z) * n;
            sHT[jj * G + g] = hn;
            dst[(b0 + g) * SS * HH + s * HH + jj] = hn;
        }
        __syncthreads();
        cur ^= 1;
    }
}

// =================================================================
// encoded = fwd + bwd (fused); enc_proj = encoded @ attn_We + be
// =================================================================
__global__ __launch_bounds__(256)
void proj_kernel(const float* __restrict__ We, const float* __restrict__ be)
{
    extern __shared__ float sm[];
    float* sWe = sm;              // 64*64
    float* sbe = sWe + HH * AA;   // 64
    float* sR  = sbe + 64;        // 64 rows * 64

    const int tid = threadIdx.x;
    for (int i = tid; i < HH * AA; i += 256) sWe[i] = We[i];
    if (tid < 64) sbe[tid] = be[tid];
    const int rbase = blockIdx.x * 64;
    for (int i = tid; i < 64 * HH; i += 256) {
        float e = g_fwd[rbase * HH + i] + g_bwd[rbase * HH + i];
        sR[i] = e;
        g_enc[rbase * HH + i] = e;
    }
    __syncthreads();

    const int a  = tid & 63;
    const int rq = tid >> 6;
    float acc[16];
    #pragma unroll
    for (int r = 0; r < 16; ++r) acc[r] = sbe[a];
    for (int k = 0; k < HH; ++k) {
        float w = sWe[k * AA + a];
        #pragma unroll
        for (int r = 0; r < 16; ++r) acc[r] += w * sR[(rq * 16 + r) * HH + k];
    }
    #pragma unroll
    for (int r = 0; r < 16; ++r)
        g_encproj[(rbase + rq * 16 + r) * AA + a] = acc[r];
}

// =================================================================
// Decoder v4: G=8, 384 threads, 1 CTA/SM @ 184 KB smem.
// R11's distributed phases (all warps in every phase) + the R12
// keepers: encoded cached in smem, GEMV weights in registers.
// New: f32x2 dproj (g-pairs), fused scores+softmax. 5 barriers/step.
// =================================================================
__global__ __launch_bounds__(384)
void dec_kernel(const int* __restrict__ tgt_ids,
                const float* __restrict__ dW, const float* __restrict__ dU,
                const float* __restrict__ db,
                const float* __restrict__ Wd, const float* __restrict__ bd,
                const float* __restrict__ av, const float* __restrict__ bv)
{
    constexpr int G = 8;
    constexpr int NT = 384;
    constexpr int EPL = AA + 1;  // 65
    extern __shared__ float sm[];
    float* sB   = sm;                  // 384
    float* sWd  = sB + 2 * GH3;        // 4096
    float* sbd  = sWd + HH * AA;       // 64
    float* sv   = sbd + AA;            // 64
    float* sEP  = sv + AA;             // 8*32*65 = 16640
    float* sEnc = sEP + G * SS * EPL;  // 8*32*64 = 16384 (same layout as g_enc)
    float* sXPx = sEnc + G * SS * HH;  // 8*192 = 1536 (gathered TD rows)
    float* sCtxT= sXPx + G * GH3;      // 64*8 = 512  ([h][g])
    float* sXPc = sCtxT + HH * G;      // 2*8*192 = 3072
    float* sHP  = sXPc + 2 * G * GH3;  // 3072
    float* sHT  = sHP + 2 * G * GH3;   // 512 ([h][g])
    float* sDP  = sHT + HH * G;        // 512
    float* sLg  = sDP + G * AA;        // 256 (normalized weights)

    const int tid = threadIdx.x;
    const int b0 = blockIdx.x * G;
    const int half = tid / 192;        // warp-uniform
    const int j    = tid - half * 192; // gate column 0..191
    const int wid  = tid >> 5;
    const int lane = tid & 31;

    // GEMV weight columns -> registers (k-split: 32 each)
    float wc[32], uu[32];
    const int k0 = half * 32;
    #pragma unroll
    for (int kk = 0; kk < 32; ++kk) {
        wc[kk] = __ldg(&dW[(HH + k0 + kk) * GH3 + j]);  // ctx half rows 64..127
        uu[kk] = __ldg(&dU[(k0 + kk) * GH3 + j]);
    }

    for (int i = tid; i < 2 * GH3; i += NT) sB[i] = db[i];
    for (int i = tid; i < HH * AA; i += NT) sWd[i] = Wd[i];
    if (tid < AA) { sbd[tid] = bd[tid]; sv[tid] = av[tid]; }
    const float bvv = bv[0];

    for (int i = tid; i < G * SS * AA; i += NT) {
        int g = i / (SS * AA);
        int rem = i - g * SS * AA;
        int s = rem >> 6;
        int a = rem & 63;
        sEP[g * SS * EPL + s * EPL + a] = g_encproj[(b0 + g) * SS * AA + rem];
    }
    // cache encoded (layout identical to global)
    for (int i = tid; i < G * SS * HH; i += NT)
        sEnc[i] = g_enc[b0 * SS * HH + i];
    __syncthreads();
    // h0 = encoded[:, 0] (transposed) — from smem
    for (int i = tid; i < G * HH; i += NT) {
        int g = i >> 6; int jj = i & 63;
        sHT[jj * G + g] = sEnc[g * SS * HH + jj];
    }
    __syncthreads();

    for (int t = 0; t < TT; ++t) {
        // ---------- P1: TD gather + h@U GEMV + dproj (f32x2 pairs) ----------
        float4 gx;
        {
            int g = tid / 48, q = tid - (tid / 48) * 48;
            int id = (t == 0) ? 1 : __ldg(&tgt_ids[(b0 + g) * TT + (t - 1)]);
            gx = __ldg((const float4*)(g_TD + id * GH3) + q);
        }
        // h @ U (register weights, depends only on prev-step sHT)
        unsigned long long hp2[4];
        {
            unsigned long long bh = (half == 0) ? pack2(sB[GH3 + j]) : 0ULL;
            #pragma unroll
            for (int p = 0; p < 4; ++p) hp2[p] = bh;
        }
        #pragma unroll
        for (int kk = 0; kk < 32; ++kk) {
            const int k = k0 + kk;
            unsigned long long u2 = pack2(uu[kk]);
            const ulonglong2* hr = (const ulonglong2*)&sHT[k * G];
            ulonglong2 h0 = hr[0], h1 = hr[1];
            fma2(hp2[0], u2, h0.x); fma2(hp2[1], u2, h0.y);
            fma2(hp2[2], u2, h1.x); fma2(hp2[3], u2, h1.y);
        }
        #pragma unroll
        for (int p = 0; p < 4; ++p) {
            float lo, hi;
            unpack2(hp2[p], lo, hi);
            sHP[(half * G + 2 * p) * GH3 + j] = lo;
            sHP[(half * G + 2 * p + 1) * GH3 + j] = hi;
        }
        // dproj: 256 pair-tasks (gp, a); g-pair packed in f32x2
        if (tid < 256) {
            int gp = tid >> 6, a = tid & 63;
            unsigned long long acc = pack2(sbd[a]);
            #pragma unroll 8
            for (int h = 0; h < HH; ++h) {
                unsigned long long h2 = *(const unsigned long long*)&sHT[h * G + 2 * gp];
                fma2(acc, pack2(sWd[h * AA + a]), h2);
            }
            float lo, hi;
            unpack2(acc, lo, hi);
            sDP[(2 * gp) * AA + a] = lo;
            sDP[(2 * gp + 1) * AA + a] = hi;
        }
        ((float4*)sXPx)[tid] = gx;
        __syncthreads();  // B1

        // ---------- P2: scores + fused warp softmax (warps 0-7) ----------
        if (wid < G) {
            const int g = wid;
            const float* ep = &sEP[g * SS * EPL + lane * EPL];
            const float* dp = &sDP[g * AA];
            float acc = bvv;
            #pragma unroll 8
            for (int a = 0; a < AA; ++a) acc += sv[a] * tanha(dp[a] + ep[a]);
            float m = acc;
            #pragma unroll
            for (int off = 16; off > 0; off >>= 1)
                m = fmaxf(m, __shfl_xor_sync(0xffffffffu, m, off));
            float e = __expf(acc - m);
            float sum = e;
            #pragma unroll
            for (int off = 16; off > 0; off >>= 1)
                sum += __shfl_xor_sync(0xffffffffu, sum, off);
            sLg[g * SS + lane] = e * __fdividef(1.0f, sum);
        }
        __syncthreads();  // B2

        // ---------- P3: context (512 tasks, from sEnc) ----------
        for (int idx = tid; idx < G * HH; idx += NT) {
            int g = idx >> 6; int h = idx & 63;
            const float* encb = &sEnc[g * SS * HH];
            float acc = 0.0f;
            #pragma unroll
            for (int s = 0; s < SS; ++s) acc += sLg[g * SS + s] * encb[s * HH + h];
            sCtxT[h * G + g] = acc;
        }
        __syncthreads();  // B3

        // ---------- P4: ctx @ Wc GEMV (register weights) ----------
        unsigned long long xc2[4];
        #pragma unroll
        for (int p = 0; p < 4; ++p) xc2[p] = 0ULL;
        #pragma unroll
        for (int kk = 0; kk < 32; ++kk) {
            const int k = k0 + kk;
            unsigned long long w2 = pack2(wc[kk]);
            const ulonglong2* cr = (const ulonglong2*)&sCtxT[k * G];
            ulonglong2 c0 = cr[0], c1 = cr[1];
            fma2(xc2[0], w2, c0.x); fma2(xc2[1], w2, c0.y);
            fma2(xc2[2], w2, c1.x); fma2(xc2[3], w2, c1.y);
        }
        #pragma unroll
        for (int p = 0; p < 4; ++p) {
            float lo, hi;
            unpack2(xc2[p], lo, hi);
            sXPc[(half * G + 2 * p) * GH3 + j] = lo;
            sXPc[(half * G + 2 * p + 1) * GH3 + j] = hi;
        }
        __syncthreads();  // B4

        // ---------- P5: gates (512 tasks) ----------
        for (int idx = tid; idx < G * HH; idx += NT) {
            int g  = idx >> 6;
            int jj = idx & 63;
            const float* XPx = &sXPx[g * GH3];
            const float* XC0 = &sXPc[g * GH3];
            const float* XC1 = &sXPc[(G + g) * GH3];
            const float* HP0 = &sHP[g * GH3];
            const float* HP1 = &sHP[(G + g) * GH3];
            float xz = XPx[jj] + XC0[jj] + XC1[jj];
            float xr = XPx[HH + jj] + XC0[HH + jj] + XC1[HH + jj];
            float xh = XPx[2*HH + jj] + XC0[2*HH + jj] + XC1[2*HH + jj];
            float hz = HP0[jj] + HP1[jj];
            float hr_ = HP0[HH + jj] + HP1[HH + jj];
            float hh = HP0[2*HH + jj] + HP1[2*HH + jj];
            float z = fsigmoid(xz + hz);
            float r = fsigmoid(xr + hr_);
            float n = ftanh(xh + r * hh);
            float hold = sHT[jj * G + g];
            float hn = z * hold + (1.0f - z) * n;
            sHT[jj * G + g] = hn;
            g_hid[(b0 + g) * TT * HH + t * HH + jj] = hn;
        }
        __syncthreads();  // B5
    }
}

// =================================================================
// logits = hidden @ out_W + out_b (transposed tile + f32x2)
// =================================================================
__global__ __launch_bounds__(256)
void out_kernel(const float* __restrict__ outW, const float* __restrict__ outb,
                float* __restrict__ out)
{
    constexpr int R = 32;
    constexpr int TIL = 4;
    constexpr int PIT = 36;
    extern __shared__ float sm[];
    float* sOW = sm;              // 64*256
    float* sOB = sOW + HH * VOC;  // 256
    float* sRT = sOB + VOC;       // 64 * 36

    const int tid = threadIdx.x;
    for (int i = tid; i < HH * VOC; i += 256) sOW[i] = outW[i];
    sOB[tid] = outb[tid];

    for (int tile = 0; tile < TIL; ++tile) {
        const int rbase = (blockIdx.x * TIL + tile) * R;
        __syncthreads();
        for (int i = tid; i < R * HH; i += 256) {
            int r = i >> 6, k = i & 63;
            sRT[k * PIT + r] = g_hid[(rbase + r) * HH + k];
        }
        __syncthreads();

        const int v = tid;
        const unsigned long long b2 = pack2(sOB[v]);
        unsigned long long acc2[16];
        #pragma unroll
        for (int p = 0; p < 16; ++p) acc2[p] = b2;

        #pragma unroll 4
        for (int k = 0; k < HH; ++k) {
            unsigned long long w2 = pack2(sOW[k * VOC + v]);
            const ulonglong2* row = (const ulonglong2*)&sRT[k * PIT];
            #pragma unroll
            for (int q = 0; q < 8; ++q) {
                ulonglong2 rp = row[q];
                fma2(acc2[2 * q], w2, rp.x);
                fma2(acc2[2 * q + 1], w2, rp.y);
            }
        }
        #pragma unroll
        for (int p = 0; p < 16; ++p) {
            float lo, hi;
            unpack2(acc2[p], lo, hi);
            out[(rbase + 2 * p) * VOC + v] = lo;
            out[(rbase + 2 * p + 1) * VOC + v] = hi;
        }
    }
}

// =================================================================
// launch
// =================================================================
extern "C" void kernel_launch(void* const* d_in, const int* in_sizes, int n_in,
                              void* d_out, int out_size)
{
    const int* src_ids = (const int*)d_in[0];   // int32 (JAX x64 disabled)
    const int* tgt_ids = (const int*)d_in[1];   // int32
    const float* src_emb = (const float*)d_in[2];
    const float* enc_Wf  = (const float*)d_in[3];
    const float* enc_Uf  = (const float*)d_in[4];
    const float* enc_bf  = (const float*)d_in[5];
    const float* enc_Wb  = (const float*)d_in[6];
    const float* enc_Ub  = (const float*)d_in[7];
    const float* enc_bb  = (const float*)d_in[8];
    const float* attn_We = (const float*)d_in[9];
    const float* attn_be = (const float*)d_in[10];
    const float* attn_Wd = (const float*)d_in[11];
    const float* attn_bd = (const float*)d_in[12];
    const float* attn_v  = (const float*)d_in[13];
    const float* attn_bv = (const float*)d_in[14];
    const float* dec_W   = (const float*)d_in[15];
    const float* dec_U   = (const float*)d_in[16];
    const float* dec_b   = (const float*)d_in[17];
    const float* out_W   = (const float*)d_in[18];
    const float* out_b   = (const float*)d_in[19];
    float* out = (float*)d_out;

    const int ENC_SMEM  = (12288 + 384 + 6144 + 1024 + 6144) * 4;                // 103936
    const int PROJ_SMEM = (4096 + 64 + 4096) * 4;                                 // 33024
    const int DEC_SMEM  = (384 + 4096 + 64 + 64 + 16640 + 16384 + 1536 + 512
                           + 3072 + 3072 + 512 + 512 + 256) * 4;                  // 188416
    const int OUT_SMEM  = (16384 + 256 + 64 * 36) * 4;                            // 75776

    cudaFuncSetAttribute(enc_kernel, cudaFuncAttributeMaxDynamicSharedMemorySize, ENC_SMEM);
    cudaFuncSetAttribute(dec_kernel, cudaFuncAttributeMaxDynamicSharedMemorySize, DEC_SMEM);
    cudaFuncSetAttribute(out_kernel, cudaFuncAttributeMaxDynamicSharedMemorySize, OUT_SMEM);

    table_kernel<<<VOC, 192>>>(src_emb, enc_Wf, enc_bf, enc_Wb, enc_bb,
                               dec_W, dec_b, out_W);
    dim3 enc_grid(BB / 16, 2);
    enc_kernel<<<enc_grid, 384, ENC_SMEM>>>(src_ids, enc_Uf, enc_bf, enc_Ub, enc_bb);
    proj_kernel<<<(BB * SS) / 64, 256, PROJ_SMEM>>>(attn_We, attn_be);
    dec_kernel<<<BB / 8, 384, DEC_SMEM>>>(tgt_ids, dec_W, dec_U, dec_b,
                                          attn_Wd, attn_bd, attn_v, attn_bv);
    out_kernel<<<(BB * TT) / (32 * 4), 256, OUT_SMEM>>>(out_W, out_b, out);
}